// round 4
// baseline (speedup 1.0000x reference)
#include <cuda_runtime.h>
#include <cuda_bf16.h>

#define N_NODES 100000
#define N_EDGES 3200000
#define F_IN 8
#define F_HID 64

// Scratch (allocation-free requirement: __device__ globals, all GPU DRAM —
// atomics guaranteed supported here, unlike the possibly host-resident d_out)
__device__ float g_deg[N_NODES];
__device__ float g_dinv[N_NODES];
__device__ __align__(16) float g_aggx[N_NODES * F_IN];   // aggregated input (layer-1 pre-linear)
__device__ float g_s[N_NODES];                           // per-node scalar after relu(h)@W2
__device__ float g_out[N_NODES];                         // accumulation target for layer 2

// ---------------------------------------------------------------------------
// 1) deg init: self-loop contributes weight 1
__global__ void k_deg_init() {
    int i = blockIdx.x * blockDim.x + threadIdx.x;
    if (i < N_NODES) g_deg[i] = 1.0f;
}

// 2) deg accumulate over edges: deg[col] += w   (edge_index is int32: JAX x64 disabled)
__global__ void k_deg_acc(const int* __restrict__ ei, const float* __restrict__ w) {
    int e = blockIdx.x * blockDim.x + threadIdx.x;
    if (e >= N_EDGES) return;
    int c = ei[N_EDGES + e];   // edge_index[1][e]
    atomicAdd(&g_deg[c], w[e]);
}

// 3) dinv = rsqrt(deg); seed aggx with self-loop term: (1/deg)*x[i]
__global__ void k_dinv_seed(const float* __restrict__ x) {
    int i = blockIdx.x * blockDim.x + threadIdx.x;
    if (i >= N_NODES) return;
    float d = g_deg[i];
    float dv = rsqrtf(d);
    g_dinv[i] = dv;
    float inv = dv * dv;            // == 1/deg
    const float4* xr = (const float4*)(x + (size_t)i * F_IN);
    float4 a = xr[0], b = xr[1];
    float4* ar = (float4*)(g_aggx + (size_t)i * F_IN);
    ar[0] = make_float4(a.x * inv, a.y * inv, a.z * inv, a.w * inv);
    ar[1] = make_float4(b.x * inv, b.y * inv, b.z * inv, b.w * inv);
}

// 4) layer-1 edge pass: aggx[col] += norm * x[row]   (8 scalar REDG/edge)
__global__ void k_layer1_edges(const int* __restrict__ ei,
                               const float* __restrict__ w,
                               const float* __restrict__ x) {
    int e = blockIdx.x * blockDim.x + threadIdx.x;
    if (e >= N_EDGES) return;
    int r = ei[e];
    int c = ei[N_EDGES + e];
    float nrm = g_dinv[r] * w[e] * g_dinv[c];
    const float4* xr = (const float4*)(x + (size_t)r * F_IN);
    float4 a = xr[0], b = xr[1];
    float* dst = g_aggx + (size_t)c * F_IN;
    atomicAdd(dst + 0, nrm * a.x);
    atomicAdd(dst + 1, nrm * a.y);
    atomicAdd(dst + 2, nrm * a.z);
    atomicAdd(dst + 3, nrm * a.w);
    atomicAdd(dst + 4, nrm * b.x);
    atomicAdd(dst + 5, nrm * b.y);
    atomicAdd(dst + 6, nrm * b.z);
    atomicAdd(dst + 7, nrm * b.w);
}

// 5) per-node dense math: h = relu(aggx@W1 + b1); s = h@W2 ; g_out = b2 + s/deg (self-loop)
__global__ void k_node_mlp(const float* __restrict__ W1,
                           const float* __restrict__ b1,
                           const float* __restrict__ W2,
                           const float* __restrict__ b2) {
    __shared__ float sW1[F_IN * F_HID];   // [k][f] layout: sW1[k*64+f]
    __shared__ float sb1[F_HID];
    __shared__ float sW2[F_HID];
    for (int t = threadIdx.x; t < F_IN * F_HID; t += blockDim.x) sW1[t] = W1[t];
    for (int t = threadIdx.x; t < F_HID; t += blockDim.x) { sb1[t] = b1[t]; sW2[t] = W2[t]; }
    __syncthreads();

    int i = blockIdx.x * blockDim.x + threadIdx.x;
    if (i >= N_NODES) return;

    float a[F_IN];
    const float4* ar = (const float4*)(g_aggx + (size_t)i * F_IN);
    float4 p = ar[0], q = ar[1];
    a[0]=p.x; a[1]=p.y; a[2]=p.z; a[3]=p.w; a[4]=q.x; a[5]=q.y; a[6]=q.z; a[7]=q.w;

    float s = 0.0f;
    #pragma unroll 8
    for (int f = 0; f < F_HID; f++) {
        float acc = sb1[f];
        #pragma unroll
        for (int k = 0; k < F_IN; k++) acc = fmaf(a[k], sW1[k * F_HID + f], acc);
        s += fmaxf(acc, 0.0f) * sW2[f];
    }
    g_s[i] = s;
    float dv = g_dinv[i];
    g_out[i] = b2[0] + dv * dv * s;   // self-loop contribution + bias
}

// 6) layer-2 edge pass: g_out[col] += norm * s[row]   (1 float/edge, GPU-DRAM scratch)
__global__ void k_layer2_edges(const int* __restrict__ ei,
                               const float* __restrict__ w) {
    int e = blockIdx.x * blockDim.x + threadIdx.x;
    if (e >= N_EDGES) return;
    int r = ei[e];
    int c = ei[N_EDGES + e];
    float nrm = g_dinv[r] * w[e] * g_dinv[c];
    atomicAdd(&g_out[c], nrm * g_s[r]);
}

// 7) plain-store copy into harness output (no atomics on d_out)
__global__ void k_copy_out(float* __restrict__ out) {
    int i = blockIdx.x * blockDim.x + threadIdx.x;
    if (i < N_NODES) out[i] = g_out[i];
}

extern "C" void kernel_launch(void* const* d_in, const int* in_sizes, int n_in,
                              void* d_out, int out_size) {
    const float* x  = (const float*)d_in[0];
    const int*   ei = (const int*)d_in[1];     // int32: JAX default x64-disabled
    const float* w  = (const float*)d_in[2];
    const float* W1 = (const float*)d_in[3];
    const float* b1 = (const float*)d_in[4];
    const float* W2 = (const float*)d_in[5];
    const float* b2 = (const float*)d_in[6];
    float* out = (float*)d_out;

    const int TB = 256;
    const int gridN = (N_NODES + TB - 1) / TB;
    const int gridE = (N_EDGES + TB - 1) / TB;

    k_deg_init<<<gridN, TB>>>();
    k_deg_acc<<<gridE, TB>>>(ei, w);
    k_dinv_seed<<<gridN, TB>>>(x);
    k_layer1_edges<<<gridE, TB>>>(ei, w, x);
    k_node_mlp<<<gridN, TB>>>(W1, b1, W2, b2);
    k_layer2_edges<<<gridE, TB>>>(ei, w);
    k_copy_out<<<gridN, TB>>>(out);
}

// round 5
// speedup vs baseline: 2.0876x; 2.0876x over previous
#include <cuda_runtime.h>
#include <cuda_bf16.h>

#define N_NODES 100000
#define N_EDGES 3200000
#define F_IN 8
#define F_HID 64

// Scratch: __device__ globals (GPU DRAM; allocation-free rule)
__device__ float g_deg[N_NODES];
__device__ float g_dinv[N_NODES];
__device__ __align__(16) float g_xs[N_NODES * F_IN];     // dinv[i] * x[i]
__device__ __align__(16) float g_acc1[N_NODES * F_IN];   // sum_{edges into c} w * xs[r]
__device__ float g_sd[N_NODES];                          // dinv[i] * s[i]
__device__ float g_acc2[N_NODES];                        // sum_{edges into c} w * sd[r]

// ---------------------------------------------------------------------------
// 1) init: zero acc1 (N*8), set deg=1 (self-loop), zero acc2
__global__ void k_init() {
    int i = blockIdx.x * blockDim.x + threadIdx.x;
    if (i < N_NODES * F_IN) g_acc1[i] = 0.0f;
    if (i < N_NODES) { g_deg[i] = 1.0f; g_acc2[i] = 0.0f; }
}

// 2) deg accumulate: deg[col] += w
__global__ void k_deg_acc(const int* __restrict__ ei, const float* __restrict__ w) {
    int e = blockIdx.x * blockDim.x + threadIdx.x;
    if (e >= N_EDGES) return;
    atomicAdd(&g_deg[ei[N_EDGES + e]], w[e]);
}

// 3) dinv = rsqrt(deg); xs = dinv * x
__global__ void k_dinv_xs(const float* __restrict__ x) {
    int i = blockIdx.x * blockDim.x + threadIdx.x;
    if (i >= N_NODES) return;
    float dv = rsqrtf(g_deg[i]);
    g_dinv[i] = dv;
    const float4* xr = (const float4*)(x + (size_t)i * F_IN);
    float4 a = xr[0], b = xr[1];
    float4* o = (float4*)(g_xs + (size_t)i * F_IN);
    o[0] = make_float4(a.x * dv, a.y * dv, a.z * dv, a.w * dv);
    o[1] = make_float4(b.x * dv, b.y * dv, b.z * dv, b.w * dv);
}

// vectorized fire-and-forget float4 reduction (sm_90a+/sm_103a)
__device__ __forceinline__ void red_add_v4(float* p, float a, float b, float c, float d) {
    asm volatile("red.global.add.v4.f32 [%0], {%1,%2,%3,%4};"
                 :: "l"(p), "f"(a), "f"(b), "f"(c), "f"(d) : "memory");
}

// 4) layer-1 edge pass: acc1[c] += w * xs[r]   (2 v4 REDs + 1 gather per edge)
__global__ void k_layer1_edges(const int* __restrict__ ei,
                               const float* __restrict__ w) {
    int e = blockIdx.x * blockDim.x + threadIdx.x;
    if (e >= N_EDGES) return;
    int r = ei[e];
    int c = ei[N_EDGES + e];
    float we = w[e];
    const float4* xr = (const float4*)(g_xs + (size_t)r * F_IN);
    float4 a = xr[0], b = xr[1];
    float* dst = g_acc1 + (size_t)c * F_IN;
    red_add_v4(dst,     we * a.x, we * a.y, we * a.z, we * a.w);
    red_add_v4(dst + 4, we * b.x, we * b.y, we * b.z, we * b.w);
}

// 5) node MLP: a = dinv*acc1 + dinv^2*x ; h = relu(a@W1+b1); s = h@W2; sd = dinv*s
__global__ void k_node_mlp(const float* __restrict__ x,
                           const float* __restrict__ W1,
                           const float* __restrict__ b1,
                           const float* __restrict__ W2) {
    __shared__ float sW1[F_IN * F_HID];   // [k][f]: sW1[k*64+f]
    __shared__ float sb1[F_HID];
    __shared__ float sW2[F_HID];
    for (int t = threadIdx.x; t < F_IN * F_HID; t += blockDim.x) sW1[t] = W1[t];
    for (int t = threadIdx.x; t < F_HID; t += blockDim.x) { sb1[t] = b1[t]; sW2[t] = W2[t]; }
    __syncthreads();

    int i = blockIdx.x * blockDim.x + threadIdx.x;
    if (i >= N_NODES) return;

    float dv = g_dinv[i];
    float dv2 = dv * dv;
    const float4* ac = (const float4*)(g_acc1 + (size_t)i * F_IN);
    const float4* xr = (const float4*)(x + (size_t)i * F_IN);
    float4 a0 = ac[0], a1 = ac[1], x0 = xr[0], x1 = xr[1];
    float a[F_IN];
    a[0] = dv * a0.x + dv2 * x0.x;  a[1] = dv * a0.y + dv2 * x0.y;
    a[2] = dv * a0.z + dv2 * x0.z;  a[3] = dv * a0.w + dv2 * x0.w;
    a[4] = dv * a1.x + dv2 * x1.x;  a[5] = dv * a1.y + dv2 * x1.y;
    a[6] = dv * a1.z + dv2 * x1.z;  a[7] = dv * a1.w + dv2 * x1.w;

    float s = 0.0f;
    #pragma unroll 8
    for (int f = 0; f < F_HID; f++) {
        float acc = sb1[f];
        #pragma unroll
        for (int k = 0; k < F_IN; k++) acc = fmaf(a[k], sW1[k * F_HID + f], acc);
        s += fmaxf(acc, 0.0f) * sW2[f];
    }
    g_sd[i] = dv * s;
}

// 6) layer-2 edge pass: acc2[c] += w * sd[r]   (1 scalar RED + 1 gather per edge)
__global__ void k_layer2_edges(const int* __restrict__ ei,
                               const float* __restrict__ w) {
    int e = blockIdx.x * blockDim.x + threadIdx.x;
    if (e >= N_EDGES) return;
    int r = ei[e];
    int c = ei[N_EDGES + e];
    atomicAdd(&g_acc2[c], w[e] * g_sd[r]);
}

// 7) epilogue: out = b2 + dinv * (acc2 + sd)   (plain stores to d_out)
__global__ void k_out(const float* __restrict__ b2, float* __restrict__ out) {
    int i = blockIdx.x * blockDim.x + threadIdx.x;
    if (i < N_NODES) out[i] = b2[0] + g_dinv[i] * (g_acc2[i] + g_sd[i]);
}

extern "C" void kernel_launch(void* const* d_in, const int* in_sizes, int n_in,
                              void* d_out, int out_size) {
    const float* x  = (const float*)d_in[0];
    const int*   ei = (const int*)d_in[1];     // int32 (JAX x64 disabled)
    const float* w  = (const float*)d_in[2];
    const float* W1 = (const float*)d_in[3];
    const float* b1 = (const float*)d_in[4];
    const float* W2 = (const float*)d_in[5];
    const float* b2 = (const float*)d_in[6];
    float* out = (float*)d_out;

    const int TB = 256;
    const int gridN  = (N_NODES + TB - 1) / TB;
    const int gridN8 = (N_NODES * F_IN + TB - 1) / TB;
    const int gridE  = (N_EDGES + TB - 1) / TB;

    k_init<<<gridN8, TB>>>();
    k_deg_acc<<<gridE, TB>>>(ei, w);
    k_dinv_xs<<<gridN, TB>>>(x);
    k_layer1_edges<<<gridE, TB>>>(ei, w);
    k_node_mlp<<<gridN, TB>>>(x, W1, b1, W2);
    k_layer2_edges<<<gridE, TB>>>(ei, w);
    k_out<<<gridN, TB>>>(b2, out);
}